// round 14
// baseline (speedup 1.0000x reference)
#include <cuda_runtime.h>
#include <cuda_fp16.h>
#include <stdint.h>

#define D_MODEL 2048
#define H_FF    1408
#define NE      8
#define NTOK    8192
#define SLOTS   16384
#define CAP     2048
#define BK      32                 // halfs per k-tile (64B rows)

#define NT1     (D_MODEL / BK)     // 64
#define NT3     (H_FF / BK)        // 44

#define NSTG    5                  // pipeline stages
#define PFD     3                  // prefetch distance (tiles ahead)

// smem stage layout (bytes): rows padded to 80B (20 words; conflict-free)
#define G1_BG   10240
#define G1_BU   15360
#define G3_B    10240
#define STG     20480
#define SMEM_SZ (NSTG * STG)       // 102400

// ---------------- scratch ----------------
__device__ int    g_cnt[NE];
__device__ int    g_tok[SLOTS];
__device__ float  g_scr[SLOTS];
__device__ int    g_posA[NTOK];
__device__ int    g_posB[NTOK];
__device__ __half g_xh [(size_t)NTOK * D_MODEL];           // fp16 [tok][d]
__device__ __half g_Wgh[(size_t)NE * H_FF * D_MODEL];      // [e][h][d]
__device__ __half g_Wuh[(size_t)NE * H_FF * D_MODEL];      // [e][h][d]
__device__ __half g_Wdh[(size_t)NE * D_MODEL * H_FF];      // [e][d][h]
__device__ __half g_Hh [(size_t)SLOTS * H_FF];             // [slot][h]
__device__ __half g_ys [(size_t)SLOTS * D_MODEL];          // scored down partials (fp16)

// ---------------- helpers ----------------
__device__ __forceinline__ uint32_t smem_u32(const void* p) {
    uint32_t a;
    asm("{ .reg .u64 t; cvta.to.shared.u64 t, %1; cvt.u32.u64 %0, t; }" : "=r"(a) : "l"(p));
    return a;
}
__device__ __forceinline__ void cp16(uint32_t dst, const void* src) {
    asm volatile("cp.async.cg.shared.global [%0], [%1], 16;" :: "r"(dst), "l"(src));
}
#define MB_INIT(a, c) asm volatile("mbarrier.init.shared.b64 [%0], %1;" :: "r"(a), "r"(c) : "memory")
#define MB_ARRIVE(a)  asm volatile("mbarrier.arrive.release.cta.shared::cta.b64 _, [%0];" :: "r"(a) : "memory")
// .noinc is load-bearing (round-10 deadlock without it)
#define CP_MB_ARRIVE(a) asm volatile("cp.async.mbarrier.arrive.noinc.shared::cta.b64 [%0];" :: "r"(a) : "memory")

__device__ __forceinline__ void mb_wait(uint32_t mbar, uint32_t parity) {
    uint32_t done;
    asm volatile(
        "{ .reg .pred p; mbarrier.try_wait.parity.acquire.cta.shared::cta.b64 p, [%1], %2; selp.b32 %0, 1, 0, p; }"
        : "=r"(done) : "r"(mbar), "r"(parity) : "memory");
    if (!done) {
        asm volatile(
            "{ .reg .pred P1;\n"
            "WL_%=: mbarrier.try_wait.parity.acquire.cta.shared::cta.b64 P1, [%0], %1, 0x989680;\n"
            "@P1 bra.uni WD_%=;\n"
            "bra.uni WL_%=;\n"
            "WD_%=: }"
            :: "r"(mbar), "r"(parity) : "memory");
    }
}

__device__ __forceinline__ void mma16(float* d, const uint32_t* a, const uint32_t* b) {
    asm volatile(
        "mma.sync.aligned.m16n8k16.row.col.f32.f16.f16.f32 "
        "{%0,%1,%2,%3}, {%4,%5,%6,%7}, {%8,%9}, {%0,%1,%2,%3};\n"
        : "+f"(d[0]), "+f"(d[1]), "+f"(d[2]), "+f"(d[3])
        : "r"(a[0]), "r"(a[1]), "r"(a[2]), "r"(a[3]), "r"(b[0]), "r"(b[1]));
}
__device__ __forceinline__ uint32_t h2u(float a, float b) {
    __half2 h = __floats2half2_rn(a, b);
    return *(uint32_t*)&h;
}

// ---------------- pre-pass kernels ----------------
__global__ void prep_kernel(const float4* __restrict__ x, int n4) {
    int i = blockIdx.x * blockDim.x + threadIdx.x;
    if (i < n4) {
        float4 v = x[i];
        uint2 o;
        o.x = h2u(v.x, v.y);
        o.y = h2u(v.z, v.w);
        ((uint2*)g_xh)[i] = o;
    }
    if (blockIdx.x == 0 && threadIdx.x < NE) g_cnt[threadIdx.x] = 0;
}

__global__ void route_kernel(const int* __restrict__ idx, const float* __restrict__ scr) {
    int s = blockIdx.x * blockDim.x + threadIdx.x;
    if (s < SLOTS) {
        int e = idx[s];
        int p = atomicAdd(&g_cnt[e], 1);
        int dst = e * CAP + p;
        g_tok[dst] = s >> 1;             // TOP_K = 2
        g_scr[dst] = scr[s];
        if (s & 1) g_posB[s >> 1] = dst; else g_posA[s >> 1] = dst;
    }
}

// transpose+convert body: src [K][N] fp32 -> dst [N][K] fp16, tile 64k x 32n
__device__ __forceinline__ void trcvt_body(const float* S, __half* D, int K, int N,
                                           int k0, int n0, int tid) {
    __shared__ float t[64][33];
    #pragma unroll
    for (int it = 0; it < 2; it++) {
        int idx = tid + it * 256;
        int kr = idx >> 3, c4 = (idx & 7) * 4;
        float4 v = *(const float4*)(S + (size_t)(k0 + kr) * N + n0 + c4);
        t[kr][c4] = v.x; t[kr][c4 + 1] = v.y; t[kr][c4 + 2] = v.z; t[kr][c4 + 3] = v.w;
    }
    __syncthreads();
    #pragma unroll
    for (int it = 0; it < 4; it++) {
        int idx = tid + it * 256;
        int n = idx >> 5, k2 = idx & 31;
        __half2 h = __floats2half2_rn(t[2 * k2][n], t[2 * k2 + 1][n]);
        ((__half2*)(D + (size_t)(n0 + n) * K + k0))[k2] = h;
    }
}

// all three weight transposes in ONE launch (z<8 Wg, z<16 Wu, else Wd)
__global__ void trcvt_all_kernel(const float* __restrict__ Wg, const float* __restrict__ Wu,
                                 const float* __restrict__ Wd,
                                 __half* __restrict__ dg, __half* __restrict__ du,
                                 __half* __restrict__ dd) {
    const int z = blockIdx.z;
    const float* S;
    __half* D;
    int K, N;
    if (z < 16) {
        const int e = z & 7;
        S = ((z < 8) ? Wg : Wu) + (size_t)e * D_MODEL * H_FF;
        D = ((z < 8) ? dg : du) + (size_t)e * H_FF * D_MODEL;
        K = D_MODEL; N = H_FF;
    } else {
        const int e = z - 16;
        S = Wd + (size_t)e * H_FF * D_MODEL;
        D = dd + (size_t)e * D_MODEL * H_FF;
        K = H_FF; N = D_MODEL;
    }
    const int k0 = blockIdx.x * 64, n0 = blockIdx.y * 32;
    if (k0 >= K || n0 >= N) return;
    trcvt_body(S, D, K, N, k0, n0, threadIdx.x);
}

// combine: y[t] = ys[posA[t]] + ys[posB[t]]   (ys fp16, y fp32)
__global__ void combine_kernel(float4* __restrict__ y) {
    int i = blockIdx.x * blockDim.x + threadIdx.x;   // over NTOK * 512
    int t = i >> 9, c = i & 511;
    const __half2* a = (const __half2*)(g_ys + (size_t)g_posA[t] * D_MODEL) + c * 2;
    const __half2* b = (const __half2*)(g_ys + (size_t)g_posB[t] * D_MODEL) + c * 2;
    __half2 a0 = a[0], a1 = a[1], b0 = b[0], b1 = b[1];
    float2 fa0 = __half22float2(a0), fa1 = __half22float2(a1);
    float2 fb0 = __half22float2(b0), fb1 = __half22float2(b1);
    float4 r;
    r.x = fa0.x + fb0.x; r.y = fa0.y + fb0.y;
    r.z = fa1.x + fb1.x; r.w = fa1.y + fb1.y;
    y[i] = r;
}

// ---------------------------------------------------------------------------
// GEMM1+2 fused (fp16). CTA: 128 slots x 64 h, gate+up. 256 threads, 8 warps
// 4x2, warp 32x32 per matrix. 5-stage mbarrier pipeline, free-running warps,
// 2 CTAs/SM. Empty barriers: count 8, lane-0-per-warp release arrive.
// ---------------------------------------------------------------------------
__global__ void __launch_bounds__(256, 2) g1_kernel() {
    extern __shared__ uint32_t sm[];
    __shared__ __align__(8) uint64_t mbs[2 * NSTG];
    const int tid = threadIdx.x, lane = tid & 31, w = tid >> 5;
    const int wm = w >> 1, wn = w & 1;                // 4x2 warp grid
    const int ql = lane >> 2, qc = lane & 3;
    const int e = blockIdx.z, bm = blockIdx.x, bn = blockIdx.y;
    const uint32_t sbase = smem_u32(sm);
    const uint32_t fullb = smem_u32(mbs), emptyb = fullb + NSTG * 8;

    if (tid == 0) {
        #pragma unroll
        for (int s = 0; s < NSTG; s++) {
            MB_INIT(fullb + 8 * s, 256);
            MB_INIT(emptyb + 8 * s, 8);   // one arrive per warp
        }
    }

    // loaders: A rows r4 and r4+64 (chunk ck); Bg/Bu row r4 (64 rows)
    const int r4 = tid >> 2, ck = tid & 3;
    const __half* ap0 = g_xh + (size_t)g_tok[e * CAP + bm * 128 + r4] * D_MODEL + ck * 8;
    const __half* ap1 = g_xh + (size_t)g_tok[e * CAP + bm * 128 + r4 + 64] * D_MODEL + ck * 8;
    const size_t bb = ((size_t)e * H_FF + (size_t)bn * 64 + r4) * D_MODEL + ck * 8;
    const __half* gp = g_Wgh + bb;
    const __half* up = g_Wuh + bb;
    const uint32_t ad0 = sbase + r4 * 80 + ck * 16, ad1 = ad0 + 64 * 80;
    const uint32_t gd = sbase + G1_BG + r4 * 80 + ck * 16;
    const uint32_t ud = sbase + G1_BU + r4 * 80 + ck * 16;

    float accg[2][4][4], accu[2][4][4];
    #pragma unroll
    for (int mi = 0; mi < 2; mi++)
        #pragma unroll
        for (int ni = 0; ni < 4; ni++)
            #pragma unroll
            for (int q = 0; q < 4; q++) { accg[mi][ni][q] = 0.f; accu[mi][ni][q] = 0.f; }

    __syncthreads();   // mbarrier init visible

    #pragma unroll
    for (int s = 0; s < PFD; s++) {
        const uint32_t so = s * STG;
        const int ko = s * BK;
        cp16(ad0 + so, ap0 + ko); cp16(ad1 + so, ap1 + ko);
        cp16(gd + so, gp + ko);   cp16(ud + so, up + ko);
        CP_MB_ARRIVE(fullb + 8 * s);
    }

    for (int kt = 0; kt < NT1; kt++) {
        const int f = kt + PFD;
        if (f < NT1) {
            const int es = f % NSTG;
            if (f >= NSTG) mb_wait(emptyb + 8 * es, (f / NSTG - 1) & 1);
            const uint32_t so = es * STG;
            const int ko = f * BK;
            cp16(ad0 + so, ap0 + ko); cp16(ad1 + so, ap1 + ko);
            cp16(gd + so, gp + ko);   cp16(ud + so, up + ko);
            CP_MB_ARRIVE(fullb + 8 * es);
        }
        const int slot = kt % NSTG;
        mb_wait(fullb + 8 * slot, (kt / NSTG) & 1);

        const uint32_t* As = sm + slot * (STG / 4);
        const uint32_t* Bg = As + G1_BG / 4;
        const uint32_t* Bu = As + G1_BU / 4;
        #pragma unroll
        for (int kk = 0; kk < 2; kk++) {
            const int kb = kk * 8 + qc;
            uint32_t af[2][4];
            #pragma unroll
            for (int mi = 0; mi < 2; mi++) {
                const int r = wm * 32 + mi * 16 + ql;
                af[mi][0] = As[r * 20 + kb];
                af[mi][1] = As[(r + 8) * 20 + kb];
                af[mi][2] = As[r * 20 + kb + 4];
                af[mi][3] = As[(r + 8) * 20 + kb + 4];
            }
            #pragma unroll
            for (int ni = 0; ni < 4; ni++) {
                const int nn = wn * 32 + ni * 8 + ql;
                uint32_t bg[2] = { Bg[nn * 20 + kb], Bg[nn * 20 + kb + 4] };
                uint32_t bu[2] = { Bu[nn * 20 + kb], Bu[nn * 20 + kb + 4] };
                #pragma unroll
                for (int mi = 0; mi < 2; mi++) {
                    mma16(accg[mi][ni], af[mi], bg);
                    mma16(accu[mi][ni], af[mi], bu);
                }
            }
        }
        if (lane == 0) MB_ARRIVE(emptyb + 8 * slot);   // warp-elected release
    }

    // epilogue: h = silu(g)*u -> fp16 H
    const size_t rowBase = (size_t)e * CAP + (size_t)bm * 128;
    const int colBase = bn * 64 + wn * 32;
    #pragma unroll
    for (int mi = 0; mi < 2; mi++)
        #pragma unroll
        for (int ni = 0; ni < 4; ni++)
            #pragma unroll
            for (int q2 = 0; q2 < 2; q2++) {
                const int r = wm * 32 + mi * 16 + ql + q2 * 8;
                float g0 = accg[mi][ni][q2 * 2],     u0 = accu[mi][ni][q2 * 2];
                float g1 = accg[mi][ni][q2 * 2 + 1], u1 = accu[mi][ni][q2 * 2 + 1];
                float h0 = (g0 / (1.f + __expf(-g0))) * u0;
                float h1 = (g1 / (1.f + __expf(-g1))) * u1;
                *(__half2*)(g_Hh + (rowBase + r) * H_FF + colBase + ni * 8 + 2 * qc) =
                    __floats2half2_rn(h0, h1);
            }
}

// ---------------------------------------------------------------------------
// GEMM3 (fp16): ys[slot] = fp16(score * (H[slot] @ Wd^T)). CTA: 128x128.
// 256 threads, 8 warps 2x4, warp 64x32. mbarrier pipeline. 2 CTAs/SM.
// ---------------------------------------------------------------------------
__global__ void __launch_bounds__(256, 2) g3_kernel() {
    extern __shared__ uint32_t sm[];
    __shared__ __align__(8) uint64_t mbs[2 * NSTG];
    __shared__ float sScr[128];
    const int tid = threadIdx.x, lane = tid & 31, w = tid >> 5;
    const int wm = w >> 2, wn = w & 3;                // 2x4 warp grid
    const int ql = lane >> 2, qc = lane & 3;
    const int e = blockIdx.z, bm = blockIdx.x, bn = blockIdx.y;
    const uint32_t sbase = smem_u32(sm);
    const uint32_t fullb = smem_u32(mbs), emptyb = fullb + NSTG * 8;

    if (tid == 0) {
        #pragma unroll
        for (int s = 0; s < NSTG; s++) {
            MB_INIT(fullb + 8 * s, 256);
            MB_INIT(emptyb + 8 * s, 8);   // one arrive per warp
        }
    }
    if (tid < 128) sScr[tid] = g_scr[e * CAP + bm * 128 + tid];

    const int r4 = tid >> 2, ck = tid & 3;
    const __half* ap0 = g_Hh + ((size_t)e * CAP + (size_t)bm * 128 + r4) * H_FF + ck * 8;
    const __half* ap1 = ap0 + (size_t)64 * H_FF;
    const size_t bb = ((size_t)e * D_MODEL + (size_t)bn * 128 + r4) * H_FF + ck * 8;
    const __half* bp0 = g_Wdh + bb;
    const __half* bp1 = g_Wdh + bb + (size_t)64 * H_FF;
    const uint32_t ad0 = sbase + r4 * 80 + ck * 16, ad1 = ad0 + 64 * 80;
    const uint32_t bd0 = sbase + G3_B + r4 * 80 + ck * 16, bd1 = bd0 + 64 * 80;

    float acc[4][4][4];
    #pragma unroll
    for (int mi = 0; mi < 4; mi++)
        #pragma unroll
        for (int ni = 0; ni < 4; ni++)
            #pragma unroll
            for (int q = 0; q < 4; q++) acc[mi][ni][q] = 0.f;

    __syncthreads();   // mbarrier init + sScr visible

    #pragma unroll
    for (int s = 0; s < PFD; s++) {
        const uint32_t so = s * STG;
        const int ko = s * BK;
        cp16(ad0 + so, ap0 + ko); cp16(ad1 + so, ap1 + ko);
        cp16(bd0 + so, bp0 + ko); cp16(bd1 + so, bp1 + ko);
        CP_MB_ARRIVE(fullb + 8 * s);
    }

    for (int kt = 0; kt < NT3; kt++) {
        const int f = kt + PFD;
        if (f < NT3) {
            const int es = f % NSTG;
            if (f >= NSTG) mb_wait(emptyb + 8 * es, (f / NSTG - 1) & 1);
            const uint32_t so = es * STG;
            const int ko = f * BK;
            cp16(ad0 + so, ap0 + ko); cp16(ad1 + so, ap1 + ko);
            cp16(bd0 + so, bp0 + ko); cp16(bd1 + so, bp1 + ko);
            CP_MB_ARRIVE(fullb + 8 * es);
        }
        const int slot = kt % NSTG;
        mb_wait(fullb + 8 * slot, (kt / NSTG) & 1);

        const uint32_t* As = sm + slot * (STG / 4);
        const uint32_t* Bs = As + G3_B / 4;
        #pragma unroll
        for (int kk = 0; kk < 2; kk++) {
            const int kb = kk * 8 + qc;
            uint32_t af[4][4];
            #pragma unroll
            for (int mi = 0; mi < 4; mi++) {
                const int r = wm * 64 + mi * 16 + ql;
                af[mi][0] = As[r * 20 + kb];
                af[mi][1] = As[(r + 8) * 20 + kb];
                af[mi][2] = As[r * 20 + kb + 4];
                af[mi][3] = As[(r + 8) * 20 + kb + 4];
            }
            #pragma unroll
            for (int ni = 0; ni < 4; ni++) {
                const int nn = wn * 32 + ni * 8 + ql;
                uint32_t bw[2] = { Bs[nn * 20 + kb], Bs[nn * 20 + kb + 4] };
                #pragma unroll
                for (int mi = 0; mi < 4; mi++)
                    mma16(acc[mi][ni], af[mi], bw);
            }
        }
        if (lane == 0) MB_ARRIVE(emptyb + 8 * slot);   // warp-elected release
    }

    // epilogue: scale by score, fp16 coalesced stores to slot buffer
    const size_t rowBase = (size_t)e * CAP + (size_t)bm * 128;
    const int colBase = bn * 128 + wn * 32;
    #pragma unroll
    for (int mi = 0; mi < 4; mi++) {
        #pragma unroll
        for (int q2 = 0; q2 < 2; q2++) {
            const int r = wm * 64 + mi * 16 + ql + q2 * 8;
            const float sc = sScr[r];
            __half* yrow = g_ys + (rowBase + r) * D_MODEL + colBase;
            #pragma unroll
            for (int ni = 0; ni < 4; ni++) {
                const int n0 = ni * 8 + 2 * qc;
                *(__half2*)(yrow + n0) = __floats2half2_rn(
                    acc[mi][ni][q2 * 2] * sc, acc[mi][ni][q2 * 2 + 1] * sc);
            }
        }
    }
}

// ---------------------------------------------------------------------------
extern "C" void kernel_launch(void* const* d_in, const int* in_sizes, int n_in,
                              void* d_out, int out_size) {
    (void)in_sizes; (void)n_in; (void)out_size;
    const float* x   = (const float*)d_in[0];
    const int*   idx = (const int*)d_in[1];
    const float* scr = (const float*)d_in[2];
    const float* Wg  = (const float*)d_in[3];
    const float* Wu  = (const float*)d_in[4];
    const float* Wd  = (const float*)d_in[5];
    float* y = (float*)d_out;

    const int n4x = NTOK * D_MODEL / 4;
    prep_kernel<<<(n4x + 255) / 256, 256>>>((const float4*)x, n4x);
    route_kernel<<<SLOTS / 256, 256>>>(idx, scr);

    __half* gg; cudaGetSymbolAddress((void**)&gg, g_Wgh);
    __half* gu; cudaGetSymbolAddress((void**)&gu, g_Wuh);
    __half* gd; cudaGetSymbolAddress((void**)&gd, g_Wdh);
    dim3 tga(D_MODEL / 64, D_MODEL / 32, 3 * NE);   // (32, 64, 24) superset grid
    trcvt_all_kernel<<<tga, 256>>>(Wg, Wu, Wd, gg, gu, gd);

    cudaFuncSetAttribute(g1_kernel, cudaFuncAttributeMaxDynamicSharedMemorySize, SMEM_SZ);
    cudaFuncSetAttribute(g3_kernel, cudaFuncAttributeMaxDynamicSharedMemorySize, SMEM_SZ);

    dim3 grid1(CAP / 128, H_FF / 64, NE);     // (16, 22, 8)
    g1_kernel<<<grid1, 256, SMEM_SZ>>>();
    dim3 grid3(CAP / 128, D_MODEL / 128, NE); // (16, 16, 8)
    g3_kernel<<<grid3, 256, SMEM_SZ>>>();

    combine_kernel<<<NTOK * (D_MODEL / 4) / 256, 256>>>((float4*)y);
}

// round 15
// speedup vs baseline: 1.4467x; 1.4467x over previous
#include <cuda_runtime.h>
#include <cuda_fp16.h>
#include <stdint.h>

#define D_MODEL 2048
#define H_FF    1408
#define NE      8
#define NTOK    8192
#define SLOTS   16384
#define CAP     2048
#define BK      32                 // halfs per k-tile (64B rows)

#define NT1     (D_MODEL / BK)     // 64
#define NT3     (H_FF / BK)        // 44

#define NSTG    5                  // pipeline stages
#define PFD     3                  // prefetch distance (tiles ahead)

// smem stage layout (bytes): rows padded to 80B (20 words; conflict-free)
#define G1_BG   10240
#define G1_BU   15360
#define G3_B    10240
#define STG     20480
#define SMEM_SZ (NSTG * STG)       // 102400

// ---------------- scratch ----------------
__device__ int    g_cnt[NE];
__device__ int    g_tok[SLOTS];
__device__ float  g_scr[SLOTS];
__device__ int    g_posA[NTOK];
__device__ int    g_posB[NTOK];
__device__ __half g_xh [(size_t)NTOK * D_MODEL];           // fp16 [tok][d]
__device__ __half g_Wgh[(size_t)NE * H_FF * D_MODEL];      // [e][h][d]
__device__ __half g_Wuh[(size_t)NE * H_FF * D_MODEL];      // [e][h][d]
__device__ __half g_Wdh[(size_t)NE * D_MODEL * H_FF];      // [e][d][h]
__device__ __half g_Hh [(size_t)SLOTS * H_FF];             // [slot][h]
__device__ __half g_ys [(size_t)SLOTS * D_MODEL];          // scored down partials (fp16)

// ---------------- helpers ----------------
__device__ __forceinline__ uint32_t smem_u32(const void* p) {
    uint32_t a;
    asm("{ .reg .u64 t; cvta.to.shared.u64 t, %1; cvt.u32.u64 %0, t; }" : "=r"(a) : "l"(p));
    return a;
}
__device__ __forceinline__ void cp16(uint32_t dst, const void* src) {
    asm volatile("cp.async.cg.shared.global [%0], [%1], 16;" :: "r"(dst), "l"(src));
}
#define MB_INIT(a, c) asm volatile("mbarrier.init.shared.b64 [%0], %1;" :: "r"(a), "r"(c) : "memory")
// plain arrive (implicit release) — r14 showed explicit .release.cta + elected
// arrives cost a per-ktile fence/divergence and regressed 45%; keep this form.
#define MB_ARRIVE(a)  asm volatile("mbarrier.arrive.shared.b64 _, [%0];" :: "r"(a) : "memory")
// .noinc is load-bearing (round-10 deadlock without it)
#define CP_MB_ARRIVE(a) asm volatile("cp.async.mbarrier.arrive.noinc.shared::cta.b64 [%0];" :: "r"(a) : "memory")

__device__ __forceinline__ void mb_wait(uint32_t mbar, uint32_t parity) {
    uint32_t done;
    asm volatile(
        "{ .reg .pred p; mbarrier.try_wait.parity.acquire.cta.shared::cta.b64 p, [%1], %2; selp.b32 %0, 1, 0, p; }"
        : "=r"(done) : "r"(mbar), "r"(parity) : "memory");
    if (!done) {
        asm volatile(
            "{ .reg .pred P1;\n"
            "WL_%=: mbarrier.try_wait.parity.acquire.cta.shared::cta.b64 P1, [%0], %1, 0x989680;\n"
            "@P1 bra.uni WD_%=;\n"
            "bra.uni WL_%=;\n"
            "WD_%=: }"
            :: "r"(mbar), "r"(parity) : "memory");
    }
}

__device__ __forceinline__ void mma16(float* d, const uint32_t* a, const uint32_t* b) {
    asm volatile(
        "mma.sync.aligned.m16n8k16.row.col.f32.f16.f16.f32 "
        "{%0,%1,%2,%3}, {%4,%5,%6,%7}, {%8,%9}, {%0,%1,%2,%3};\n"
        : "+f"(d[0]), "+f"(d[1]), "+f"(d[2]), "+f"(d[3])
        : "r"(a[0]), "r"(a[1]), "r"(a[2]), "r"(a[3]), "r"(b[0]), "r"(b[1]));
}
__device__ __forceinline__ uint32_t h2u(float a, float b) {
    __half2 h = __floats2half2_rn(a, b);
    return *(uint32_t*)&h;
}

// ---------------- pre-pass kernels ----------------
__global__ void prep_kernel(const float4* __restrict__ x, int n4) {
    int i = blockIdx.x * blockDim.x + threadIdx.x;
    if (i < n4) {
        float4 v = x[i];
        uint2 o;
        o.x = h2u(v.x, v.y);
        o.y = h2u(v.z, v.w);
        ((uint2*)g_xh)[i] = o;
    }
    if (blockIdx.x == 0 && threadIdx.x < NE) g_cnt[threadIdx.x] = 0;
}

__global__ void route_kernel(const int* __restrict__ idx, const float* __restrict__ scr) {
    int s = blockIdx.x * blockDim.x + threadIdx.x;
    if (s < SLOTS) {
        int e = idx[s];
        int p = atomicAdd(&g_cnt[e], 1);
        int dst = e * CAP + p;
        g_tok[dst] = s >> 1;             // TOP_K = 2
        g_scr[dst] = scr[s];
        if (s & 1) g_posB[s >> 1] = dst; else g_posA[s >> 1] = dst;
    }
}

// transpose+convert body: src [K][N] fp32 -> dst [N][K] fp16, tile 64k x 32n
__device__ __forceinline__ void trcvt_body(const float* S, __half* D, int K, int N,
                                           int k0, int n0, int tid) {
    __shared__ float t[64][33];
    #pragma unroll
    for (int it = 0; it < 2; it++) {
        int idx = tid + it * 256;
        int kr = idx >> 3, c4 = (idx & 7) * 4;
        float4 v = *(const float4*)(S + (size_t)(k0 + kr) * N + n0 + c4);
        t[kr][c4] = v.x; t[kr][c4 + 1] = v.y; t[kr][c4 + 2] = v.z; t[kr][c4 + 3] = v.w;
    }
    __syncthreads();
    #pragma unroll
    for (int it = 0; it < 4; it++) {
        int idx = tid + it * 256;
        int n = idx >> 5, k2 = idx & 31;
        __half2 h = __floats2half2_rn(t[2 * k2][n], t[2 * k2 + 1][n]);
        ((__half2*)(D + (size_t)(n0 + n) * K + k0))[k2] = h;
    }
}

// all three weight transposes in ONE launch (z<8 Wg, z<16 Wu, else Wd)
__global__ void trcvt_all_kernel(const float* __restrict__ Wg, const float* __restrict__ Wu,
                                 const float* __restrict__ Wd,
                                 __half* __restrict__ dg, __half* __restrict__ du,
                                 __half* __restrict__ dd) {
    const int z = blockIdx.z;
    const float* S;
    __half* D;
    int K, N;
    if (z < 16) {
        const int e = z & 7;
        S = ((z < 8) ? Wg : Wu) + (size_t)e * D_MODEL * H_FF;
        D = ((z < 8) ? dg : du) + (size_t)e * H_FF * D_MODEL;
        K = D_MODEL; N = H_FF;
    } else {
        const int e = z - 16;
        S = Wd + (size_t)e * H_FF * D_MODEL;
        D = dd + (size_t)e * D_MODEL * H_FF;
        K = H_FF; N = D_MODEL;
    }
    const int k0 = blockIdx.x * 64, n0 = blockIdx.y * 32;
    if (k0 >= K || n0 >= N) return;
    trcvt_body(S, D, K, N, k0, n0, threadIdx.x);
}

// combine: y[t] = ys[posA[t]] + ys[posB[t]]   (ys fp16, y fp32)
__global__ void combine_kernel(float4* __restrict__ y) {
    int i = blockIdx.x * blockDim.x + threadIdx.x;   // over NTOK * 512
    int t = i >> 9, c = i & 511;
    const __half2* a = (const __half2*)(g_ys + (size_t)g_posA[t] * D_MODEL) + c * 2;
    const __half2* b = (const __half2*)(g_ys + (size_t)g_posB[t] * D_MODEL) + c * 2;
    __half2 a0 = a[0], a1 = a[1], b0 = b[0], b1 = b[1];
    float2 fa0 = __half22float2(a0), fa1 = __half22float2(a1);
    float2 fb0 = __half22float2(b0), fb1 = __half22float2(b1);
    float4 r;
    r.x = fa0.x + fb0.x; r.y = fa0.y + fb0.y;
    r.z = fa1.x + fb1.x; r.w = fa1.y + fb1.y;
    y[i] = r;
}

// ---------------------------------------------------------------------------
// GEMM1+2 fused (fp16). CTA: 128 slots x 64 h, gate+up. 256 threads, 8 warps
// 4x2, warp 32x32 per matrix. 5-stage mbarrier pipeline, free-running warps,
// 2 CTAs/SM. (r13-validated best configuration)
// ---------------------------------------------------------------------------
__global__ void __launch_bounds__(256, 2) g1_kernel() {
    extern __shared__ uint32_t sm[];
    __shared__ __align__(8) uint64_t mbs[2 * NSTG];
    const int tid = threadIdx.x, lane = tid & 31, w = tid >> 5;
    const int wm = w >> 1, wn = w & 1;                // 4x2 warp grid
    const int ql = lane >> 2, qc = lane & 3;
    const int e = blockIdx.z, bm = blockIdx.x, bn = blockIdx.y;
    const uint32_t sbase = smem_u32(sm);
    const uint32_t fullb = smem_u32(mbs), emptyb = fullb + NSTG * 8;

    if (tid == 0) {
        #pragma unroll
        for (int s = 0; s < NSTG; s++) {
            MB_INIT(fullb + 8 * s, 256);
            MB_INIT(emptyb + 8 * s, 256);
        }
    }

    // loaders: A rows r4 and r4+64 (chunk ck); Bg/Bu row r4 (64 rows)
    const int r4 = tid >> 2, ck = tid & 3;
    const __half* ap0 = g_xh + (size_t)g_tok[e * CAP + bm * 128 + r4] * D_MODEL + ck * 8;
    const __half* ap1 = g_xh + (size_t)g_tok[e * CAP + bm * 128 + r4 + 64] * D_MODEL + ck * 8;
    const size_t bb = ((size_t)e * H_FF + (size_t)bn * 64 + r4) * D_MODEL + ck * 8;
    const __half* gp = g_Wgh + bb;
    const __half* up = g_Wuh + bb;
    const uint32_t ad0 = sbase + r4 * 80 + ck * 16, ad1 = ad0 + 64 * 80;
    const uint32_t gd = sbase + G1_BG + r4 * 80 + ck * 16;
    const uint32_t ud = sbase + G1_BU + r4 * 80 + ck * 16;

    float accg[2][4][4], accu[2][4][4];
    #pragma unroll
    for (int mi = 0; mi < 2; mi++)
        #pragma unroll
        for (int ni = 0; ni < 4; ni++)
            #pragma unroll
            for (int q = 0; q < 4; q++) { accg[mi][ni][q] = 0.f; accu[mi][ni][q] = 0.f; }

    __syncthreads();   // mbarrier init visible

    #pragma unroll
    for (int s = 0; s < PFD; s++) {
        const uint32_t so = s * STG;
        const int ko = s * BK;
        cp16(ad0 + so, ap0 + ko); cp16(ad1 + so, ap1 + ko);
        cp16(gd + so, gp + ko);   cp16(ud + so, up + ko);
        CP_MB_ARRIVE(fullb + 8 * s);
    }

    for (int kt = 0; kt < NT1; kt++) {
        const int f = kt + PFD;
        if (f < NT1) {
            const int es = f % NSTG;
            if (f >= NSTG) mb_wait(emptyb + 8 * es, (f / NSTG - 1) & 1);
            const uint32_t so = es * STG;
            const int ko = f * BK;
            cp16(ad0 + so, ap0 + ko); cp16(ad1 + so, ap1 + ko);
            cp16(gd + so, gp + ko);   cp16(ud + so, up + ko);
            CP_MB_ARRIVE(fullb + 8 * es);
        }
        const int slot = kt % NSTG;
        mb_wait(fullb + 8 * slot, (kt / NSTG) & 1);

        const uint32_t* As = sm + slot * (STG / 4);
        const uint32_t* Bg = As + G1_BG / 4;
        const uint32_t* Bu = As + G1_BU / 4;
        #pragma unroll
        for (int kk = 0; kk < 2; kk++) {
            const int kb = kk * 8 + qc;
            uint32_t af[2][4];
            #pragma unroll
            for (int mi = 0; mi < 2; mi++) {
                const int r = wm * 32 + mi * 16 + ql;
                af[mi][0] = As[r * 20 + kb];
                af[mi][1] = As[(r + 8) * 20 + kb];
                af[mi][2] = As[r * 20 + kb + 4];
                af[mi][3] = As[(r + 8) * 20 + kb + 4];
            }
            #pragma unroll
            for (int ni = 0; ni < 4; ni++) {
                const int nn = wn * 32 + ni * 8 + ql;
                uint32_t bg[2] = { Bg[nn * 20 + kb], Bg[nn * 20 + kb + 4] };
                uint32_t bu[2] = { Bu[nn * 20 + kb], Bu[nn * 20 + kb + 4] };
                #pragma unroll
                for (int mi = 0; mi < 2; mi++) {
                    mma16(accg[mi][ni], af[mi], bg);
                    mma16(accu[mi][ni], af[mi], bu);
                }
            }
        }
        MB_ARRIVE(emptyb + 8 * slot);
    }

    // epilogue: h = silu(g)*u -> fp16 H
    const size_t rowBase = (size_t)e * CAP + (size_t)bm * 128;
    const int colBase = bn * 64 + wn * 32;
    #pragma unroll
    for (int mi = 0; mi < 2; mi++)
        #pragma unroll
        for (int ni = 0; ni < 4; ni++)
            #pragma unroll
            for (int q2 = 0; q2 < 2; q2++) {
                const int r = wm * 32 + mi * 16 + ql + q2 * 8;
                float g0 = accg[mi][ni][q2 * 2],     u0 = accu[mi][ni][q2 * 2];
                float g1 = accg[mi][ni][q2 * 2 + 1], u1 = accu[mi][ni][q2 * 2 + 1];
                float h0 = (g0 / (1.f + __expf(-g0))) * u0;
                float h1 = (g1 / (1.f + __expf(-g1))) * u1;
                *(__half2*)(g_Hh + (rowBase + r) * H_FF + colBase + ni * 8 + 2 * qc) =
                    __floats2half2_rn(h0, h1);
            }
}

// ---------------------------------------------------------------------------
// GEMM3 (fp16): ys[slot] = fp16(score * (H[slot] @ Wd^T)). CTA: 128x128.
// 256 threads, 8 warps 2x4, warp 64x32. mbarrier pipeline. 2 CTAs/SM.
// ---------------------------------------------------------------------------
__global__ void __launch_bounds__(256, 2) g3_kernel() {
    extern __shared__ uint32_t sm[];
    __shared__ __align__(8) uint64_t mbs[2 * NSTG];
    __shared__ float sScr[128];
    const int tid = threadIdx.x, lane = tid & 31, w = tid >> 5;
    const int wm = w >> 2, wn = w & 3;                // 2x4 warp grid
    const int ql = lane >> 2, qc = lane & 3;
    const int e = blockIdx.z, bm = blockIdx.x, bn = blockIdx.y;
    const uint32_t sbase = smem_u32(sm);
    const uint32_t fullb = smem_u32(mbs), emptyb = fullb + NSTG * 8;

    if (tid == 0) {
        #pragma unroll
        for (int s = 0; s < NSTG; s++) {
            MB_INIT(fullb + 8 * s, 256);
            MB_INIT(emptyb + 8 * s, 256);
        }
    }
    if (tid < 128) sScr[tid] = g_scr[e * CAP + bm * 128 + tid];

    const int r4 = tid >> 2, ck = tid & 3;
    const __half* ap0 = g_Hh + ((size_t)e * CAP + (size_t)bm * 128 + r4) * H_FF + ck * 8;
    const __half* ap1 = ap0 + (size_t)64 * H_FF;
    const size_t bb = ((size_t)e * D_MODEL + (size_t)bn * 128 + r4) * H_FF + ck * 8;
    const __half* bp0 = g_Wdh + bb;
    const __half* bp1 = g_Wdh + bb + (size_t)64 * H_FF;
    const uint32_t ad0 = sbase + r4 * 80 + ck * 16, ad1 = ad0 + 64 * 80;
    const uint32_t bd0 = sbase + G3_B + r4 * 80 + ck * 16, bd1 = bd0 + 64 * 80;

    float acc[4][4][4];
    #pragma unroll
    for (int mi = 0; mi < 4; mi++)
        #pragma unroll
        for (int ni = 0; ni < 4; ni++)
            #pragma unroll
            for (int q = 0; q < 4; q++) acc[mi][ni][q] = 0.f;

    __syncthreads();   // mbarrier init + sScr visible

    #pragma unroll
    for (int s = 0; s < PFD; s++) {
        const uint32_t so = s * STG;
        const int ko = s * BK;
        cp16(ad0 + so, ap0 + ko); cp16(ad1 + so, ap1 + ko);
        cp16(bd0 + so, bp0 + ko); cp16(bd1 + so, bp1 + ko);
        CP_MB_ARRIVE(fullb + 8 * s);
    }

    for (int kt = 0; kt < NT3; kt++) {
        const int f = kt + PFD;
        if (f < NT3) {
            const int es = f % NSTG;
            if (f >= NSTG) mb_wait(emptyb + 8 * es, (f / NSTG - 1) & 1);
            const uint32_t so = es * STG;
            const int ko = f * BK;
            cp16(ad0 + so, ap0 + ko); cp16(ad1 + so, ap1 + ko);
            cp16(bd0 + so, bp0 + ko); cp16(bd1 + so, bp1 + ko);
            CP_MB_ARRIVE(fullb + 8 * es);
        }
        const int slot = kt % NSTG;
        mb_wait(fullb + 8 * slot, (kt / NSTG) & 1);

        const uint32_t* As = sm + slot * (STG / 4);
        const uint32_t* Bs = As + G3_B / 4;
        #pragma unroll
        for (int kk = 0; kk < 2; kk++) {
            const int kb = kk * 8 + qc;
            uint32_t af[4][4];
            #pragma unroll
            for (int mi = 0; mi < 4; mi++) {
                const int r = wm * 64 + mi * 16 + ql;
                af[mi][0] = As[r * 20 + kb];
                af[mi][1] = As[(r + 8) * 20 + kb];
                af[mi][2] = As[r * 20 + kb + 4];
                af[mi][3] = As[(r + 8) * 20 + kb + 4];
            }
            #pragma unroll
            for (int ni = 0; ni < 4; ni++) {
                const int nn = wn * 32 + ni * 8 + ql;
                uint32_t bw[2] = { Bs[nn * 20 + kb], Bs[nn * 20 + kb + 4] };
                #pragma unroll
                for (int mi = 0; mi < 4; mi++)
                    mma16(acc[mi][ni], af[mi], bw);
            }
        }
        MB_ARRIVE(emptyb + 8 * slot);
    }

    // epilogue: scale by score, fp16 coalesced stores to slot buffer
    const size_t rowBase = (size_t)e * CAP + (size_t)bm * 128;
    const int colBase = bn * 128 + wn * 32;
    #pragma unroll
    for (int mi = 0; mi < 4; mi++) {
        #pragma unroll
        for (int q2 = 0; q2 < 2; q2++) {
            const int r = wm * 64 + mi * 16 + ql + q2 * 8;
            const float sc = sScr[r];
            __half* yrow = g_ys + (rowBase + r) * D_MODEL + colBase;
            #pragma unroll
            for (int ni = 0; ni < 4; ni++) {
                const int n0 = ni * 8 + 2 * qc;
                *(__half2*)(yrow + n0) = __floats2half2_rn(
                    acc[mi][ni][q2 * 2] * sc, acc[mi][ni][q2 * 2 + 1] * sc);
            }
        }
    }
}

// ---------------------------------------------------------------------------
extern "C" void kernel_launch(void* const* d_in, const int* in_sizes, int n_in,
                              void* d_out, int out_size) {
    (void)in_sizes; (void)n_in; (void)out_size;
    const float* x   = (const float*)d_in[0];
    const int*   idx = (const int*)d_in[1];
    const float* scr = (const float*)d_in[2];
    const float* Wg  = (const float*)d_in[3];
    const float* Wu  = (const float*)d_in[4];
    const float* Wd  = (const float*)d_in[5];
    float* y = (float*)d_out;

    const int n4x = NTOK * D_MODEL / 4;
    prep_kernel<<<(n4x + 255) / 256, 256>>>((const float4*)x, n4x);
    route_kernel<<<SLOTS / 256, 256>>>(idx, scr);

    __half* gg; cudaGetSymbolAddress((void**)&gg, g_Wgh);
    __half* gu; cudaGetSymbolAddress((void**)&gu, g_Wuh);
    __half* gd; cudaGetSymbolAddress((void**)&gd, g_Wdh);
    dim3 tga(D_MODEL / 64, D_MODEL / 32, 3 * NE);   // (32, 64, 24) superset grid
    trcvt_all_kernel<<<tga, 256>>>(Wg, Wu, Wd, gg, gu, gd);

    cudaFuncSetAttribute(g1_kernel, cudaFuncAttributeMaxDynamicSharedMemorySize, SMEM_SZ);
    cudaFuncSetAttribute(g3_kernel, cudaFuncAttributeMaxDynamicSharedMemorySize, SMEM_SZ);

    dim3 grid1(CAP / 128, H_FF / 64, NE);     // (16, 22, 8)
    g1_kernel<<<grid1, 256, SMEM_SZ>>>();
    dim3 grid3(CAP / 128, D_MODEL / 128, NE); // (16, 16, 8)
    g3_kernel<<<grid3, 256, SMEM_SZ>>>();

    combine_kernel<<<NTOK * (D_MODEL / 4) / 256, 256>>>((float4*)y);
}

// round 16
// speedup vs baseline: 1.5003x; 1.0370x over previous
#include <cuda_runtime.h>
#include <cuda_fp16.h>
#include <stdint.h>

#define D_MODEL 2048
#define H_FF    1408
#define NE      8
#define NTOK    8192
#define SLOTS   16384
#define CAP     2048
#define BK      32                 // halfs per k-tile (64B rows)

#define NT1     (D_MODEL / BK)     // 64
#define NT3     (H_FF / BK)        // 44

#define NSTG    5                  // pipeline stages
#define PFD     2                  // prefetch distance; slip bound = NSTG-PFD = 3

// smem stage layout (bytes): rows padded to 80B (20 words; conflict-free)
#define G1_BG   10240
#define G1_BU   15360
#define G3_B    10240
#define STG     20480
#define SMEM_SZ (NSTG * STG)       // 102400

// ---------------- scratch ----------------
__device__ int    g_cnt[NE];
__device__ int    g_tok[SLOTS];
__device__ float  g_scr[SLOTS];
__device__ int    g_posA[NTOK];
__device__ int    g_posB[NTOK];
__device__ __half g_xh [(size_t)NTOK * D_MODEL];           // fp16 [tok][d]
__device__ __half g_Wgh[(size_t)NE * H_FF * D_MODEL];      // [e][h][d]
__device__ __half g_Wuh[(size_t)NE * H_FF * D_MODEL];      // [e][h][d]
__device__ __half g_Wdh[(size_t)NE * D_MODEL * H_FF];      // [e][d][h]
__device__ __half g_Hh [(size_t)SLOTS * H_FF];             // [slot][h]
__device__ __half g_ys [(size_t)SLOTS * D_MODEL];          // scored down partials (fp16)

// ---------------- helpers ----------------
__device__ __forceinline__ uint32_t smem_u32(const void* p) {
    uint32_t a;
    asm("{ .reg .u64 t; cvta.to.shared.u64 t, %1; cvt.u32.u64 %0, t; }" : "=r"(a) : "l"(p));
    return a;
}
__device__ __forceinline__ void cp16(uint32_t dst, const void* src) {
    asm volatile("cp.async.cg.shared.global [%0], [%1], 16;" :: "r"(dst), "l"(src));
}
#define MB_INIT(a, c) asm volatile("mbarrier.init.shared.b64 [%0], %1;" :: "r"(a), "r"(c) : "memory")
// plain arrive (implicit release) — r14 showed explicit .release.cta + elected
// arrives cost a per-ktile fence/divergence and regressed 45%; keep this form.
#define MB_ARRIVE(a)  asm volatile("mbarrier.arrive.shared.b64 _, [%0];" :: "r"(a) : "memory")
// .noinc is load-bearing (round-10 deadlock without it)
#define CP_MB_ARRIVE(a) asm volatile("cp.async.mbarrier.arrive.noinc.shared::cta.b64 [%0];" :: "r"(a) : "memory")

__device__ __forceinline__ void mb_wait(uint32_t mbar, uint32_t parity) {
    uint32_t done;
    asm volatile(
        "{ .reg .pred p; mbarrier.try_wait.parity.acquire.cta.shared::cta.b64 p, [%1], %2; selp.b32 %0, 1, 0, p; }"
        : "=r"(done) : "r"(mbar), "r"(parity) : "memory");
    if (!done) {
        asm volatile(
            "{ .reg .pred P1;\n"
            "WL_%=: mbarrier.try_wait.parity.acquire.cta.shared::cta.b64 P1, [%0], %1, 0x989680;\n"
            "@P1 bra.uni WD_%=;\n"
            "bra.uni WL_%=;\n"
            "WD_%=: }"
            :: "r"(mbar), "r"(parity) : "memory");
    }
}

__device__ __forceinline__ void mma16(float* d, const uint32_t* a, const uint32_t* b) {
    asm volatile(
        "mma.sync.aligned.m16n8k16.row.col.f32.f16.f16.f32 "
        "{%0,%1,%2,%3}, {%4,%5,%6,%7}, {%8,%9}, {%0,%1,%2,%3};\n"
        : "+f"(d[0]), "+f"(d[1]), "+f"(d[2]), "+f"(d[3])
        : "r"(a[0]), "r"(a[1]), "r"(a[2]), "r"(a[3]), "r"(b[0]), "r"(b[1]));
}
__device__ __forceinline__ uint32_t h2u(float a, float b) {
    __half2 h = __floats2half2_rn(a, b);
    return *(uint32_t*)&h;
}

// ---------------- pre-pass kernels ----------------
__global__ void prep_kernel(const float4* __restrict__ x, int n4) {
    int i = blockIdx.x * blockDim.x + threadIdx.x;
    if (i < n4) {
        float4 v = x[i];
        uint2 o;
        o.x = h2u(v.x, v.y);
        o.y = h2u(v.z, v.w);
        ((uint2*)g_xh)[i] = o;
    }
    if (blockIdx.x == 0 && threadIdx.x < NE) g_cnt[threadIdx.x] = 0;
}

__global__ void route_kernel(const int* __restrict__ idx, const float* __restrict__ scr) {
    int s = blockIdx.x * blockDim.x + threadIdx.x;
    if (s < SLOTS) {
        int e = idx[s];
        int p = atomicAdd(&g_cnt[e], 1);
        int dst = e * CAP + p;
        g_tok[dst] = s >> 1;             // TOP_K = 2
        g_scr[dst] = scr[s];
        if (s & 1) g_posB[s >> 1] = dst; else g_posA[s >> 1] = dst;
    }
}

// transpose+convert body: src [K][N] fp32 -> dst [N][K] fp16, tile 64k x 32n
__device__ __forceinline__ void trcvt_body(const float* S, __half* D, int K, int N,
                                           int k0, int n0, int tid) {
    __shared__ float t[64][33];
    #pragma unroll
    for (int it = 0; it < 2; it++) {
        int idx = tid + it * 256;
        int kr = idx >> 3, c4 = (idx & 7) * 4;
        float4 v = *(const float4*)(S + (size_t)(k0 + kr) * N + n0 + c4);
        t[kr][c4] = v.x; t[kr][c4 + 1] = v.y; t[kr][c4 + 2] = v.z; t[kr][c4 + 3] = v.w;
    }
    __syncthreads();
    #pragma unroll
    for (int it = 0; it < 4; it++) {
        int idx = tid + it * 256;
        int n = idx >> 5, k2 = idx & 31;
        __half2 h = __floats2half2_rn(t[2 * k2][n], t[2 * k2 + 1][n]);
        ((__half2*)(D + (size_t)(n0 + n) * K + k0))[k2] = h;
    }
}

// all three weight transposes in ONE launch (z<8 Wg, z<16 Wu, else Wd)
__global__ void trcvt_all_kernel(const float* __restrict__ Wg, const float* __restrict__ Wu,
                                 const float* __restrict__ Wd,
                                 __half* __restrict__ dg, __half* __restrict__ du,
                                 __half* __restrict__ dd) {
    const int z = blockIdx.z;
    const float* S;
    __half* D;
    int K, N;
    if (z < 16) {
        const int e = z & 7;
        S = ((z < 8) ? Wg : Wu) + (size_t)e * D_MODEL * H_FF;
        D = ((z < 8) ? dg : du) + (size_t)e * H_FF * D_MODEL;
        K = D_MODEL; N = H_FF;
    } else {
        const int e = z - 16;
        S = Wd + (size_t)e * H_FF * D_MODEL;
        D = dd + (size_t)e * D_MODEL * H_FF;
        K = H_FF; N = D_MODEL;
    }
    const int k0 = blockIdx.x * 64, n0 = blockIdx.y * 32;
    if (k0 >= K || n0 >= N) return;
    trcvt_body(S, D, K, N, k0, n0, threadIdx.x);
}

// combine: y[t] = ys[posA[t]] + ys[posB[t]]   (ys fp16, y fp32)
__global__ void combine_kernel(float4* __restrict__ y) {
    int i = blockIdx.x * blockDim.x + threadIdx.x;   // over NTOK * 512
    int t = i >> 9, c = i & 511;
    const __half2* a = (const __half2*)(g_ys + (size_t)g_posA[t] * D_MODEL) + c * 2;
    const __half2* b = (const __half2*)(g_ys + (size_t)g_posB[t] * D_MODEL) + c * 2;
    __half2 a0 = a[0], a1 = a[1], b0 = b[0], b1 = b[1];
    float2 fa0 = __half22float2(a0), fa1 = __half22float2(a1);
    float2 fb0 = __half22float2(b0), fb1 = __half22float2(b1);
    float4 r;
    r.x = fa0.x + fb0.x; r.y = fa0.y + fb0.y;
    r.z = fa1.x + fb1.x; r.w = fa1.y + fb1.y;
    y[i] = r;
}

// ---------------------------------------------------------------------------
// GEMM1+2 fused (fp16). CTA: 128 slots x 64 h, gate+up. 256 threads, 8 warps
// 4x2, warp 32x32 per matrix. 5-stage mbarrier pipeline, free-running warps
// (slip bound NSTG-PFD = 3), 2 CTAs/SM.
// ---------------------------------------------------------------------------
__global__ void __launch_bounds__(256, 2) g1_kernel() {
    extern __shared__ uint32_t sm[];
    __shared__ __align__(8) uint64_t mbs[2 * NSTG];
    const int tid = threadIdx.x, lane = tid & 31, w = tid >> 5;
    const int wm = w >> 1, wn = w & 1;                // 4x2 warp grid
    const int ql = lane >> 2, qc = lane & 3;
    const int e = blockIdx.z, bm = blockIdx.x, bn = blockIdx.y;
    const uint32_t sbase = smem_u32(sm);
    const uint32_t fullb = smem_u32(mbs), emptyb = fullb + NSTG * 8;

    if (tid == 0) {
        #pragma unroll
        for (int s = 0; s < NSTG; s++) {
            MB_INIT(fullb + 8 * s, 256);
            MB_INIT(emptyb + 8 * s, 256);
        }
    }

    // loaders: A rows r4 and r4+64 (chunk ck); Bg/Bu row r4 (64 rows)
    const int r4 = tid >> 2, ck = tid & 3;
    const __half* ap0 = g_xh + (size_t)g_tok[e * CAP + bm * 128 + r4] * D_MODEL + ck * 8;
    const __half* ap1 = g_xh + (size_t)g_tok[e * CAP + bm * 128 + r4 + 64] * D_MODEL + ck * 8;
    const size_t bb = ((size_t)e * H_FF + (size_t)bn * 64 + r4) * D_MODEL + ck * 8;
    const __half* gp = g_Wgh + bb;
    const __half* up = g_Wuh + bb;
    const uint32_t ad0 = sbase + r4 * 80 + ck * 16, ad1 = ad0 + 64 * 80;
    const uint32_t gd = sbase + G1_BG + r4 * 80 + ck * 16;
    const uint32_t ud = sbase + G1_BU + r4 * 80 + ck * 16;

    float accg[2][4][4], accu[2][4][4];
    #pragma unroll
    for (int mi = 0; mi < 2; mi++)
        #pragma unroll
        for (int ni = 0; ni < 4; ni++)
            #pragma unroll
            for (int q = 0; q < 4; q++) { accg[mi][ni][q] = 0.f; accu[mi][ni][q] = 0.f; }

    __syncthreads();   // mbarrier init visible

    #pragma unroll
    for (int s = 0; s < PFD; s++) {
        const uint32_t so = s * STG;
        const int ko = s * BK;
        cp16(ad0 + so, ap0 + ko); cp16(ad1 + so, ap1 + ko);
        cp16(gd + so, gp + ko);   cp16(ud + so, up + ko);
        CP_MB_ARRIVE(fullb + 8 * s);
    }

    for (int kt = 0; kt < NT1; kt++) {
        const int f = kt + PFD;
        if (f < NT1) {
            const int es = f % NSTG;
            if (f >= NSTG) mb_wait(emptyb + 8 * es, (f / NSTG - 1) & 1);
            const uint32_t so = es * STG;
            const int ko = f * BK;
            cp16(ad0 + so, ap0 + ko); cp16(ad1 + so, ap1 + ko);
            cp16(gd + so, gp + ko);   cp16(ud + so, up + ko);
            CP_MB_ARRIVE(fullb + 8 * es);
        }
        const int slot = kt % NSTG;
        mb_wait(fullb + 8 * slot, (kt / NSTG) & 1);

        const uint32_t* As = sm + slot * (STG / 4);
        const uint32_t* Bg = As + G1_BG / 4;
        const uint32_t* Bu = As + G1_BU / 4;
        #pragma unroll
        for (int kk = 0; kk < 2; kk++) {
            const int kb = kk * 8 + qc;
            uint32_t af[2][4];
            #pragma unroll
            for (int mi = 0; mi < 2; mi++) {
                const int r = wm * 32 + mi * 16 + ql;
                af[mi][0] = As[r * 20 + kb];
                af[mi][1] = As[(r + 8) * 20 + kb];
                af[mi][2] = As[r * 20 + kb + 4];
                af[mi][3] = As[(r + 8) * 20 + kb + 4];
            }
            #pragma unroll
            for (int ni = 0; ni < 4; ni++) {
                const int nn = wn * 32 + ni * 8 + ql;
                uint32_t bg[2] = { Bg[nn * 20 + kb], Bg[nn * 20 + kb + 4] };
                uint32_t bu[2] = { Bu[nn * 20 + kb], Bu[nn * 20 + kb + 4] };
                #pragma unroll
                for (int mi = 0; mi < 2; mi++) {
                    mma16(accg[mi][ni], af[mi], bg);
                    mma16(accu[mi][ni], af[mi], bu);
                }
            }
        }
        MB_ARRIVE(emptyb + 8 * slot);
    }

    // epilogue: h = silu(g)*u -> fp16 H
    const size_t rowBase = (size_t)e * CAP + (size_t)bm * 128;
    const int colBase = bn * 64 + wn * 32;
    #pragma unroll
    for (int mi = 0; mi < 2; mi++)
        #pragma unroll
        for (int ni = 0; ni < 4; ni++)
            #pragma unroll
            for (int q2 = 0; q2 < 2; q2++) {
                const int r = wm * 32 + mi * 16 + ql + q2 * 8;
                float g0 = accg[mi][ni][q2 * 2],     u0 = accu[mi][ni][q2 * 2];
                float g1 = accg[mi][ni][q2 * 2 + 1], u1 = accu[mi][ni][q2 * 2 + 1];
                float h0 = (g0 / (1.f + __expf(-g0))) * u0;
                float h1 = (g1 / (1.f + __expf(-g1))) * u1;
                *(__half2*)(g_Hh + (rowBase + r) * H_FF + colBase + ni * 8 + 2 * qc) =
                    __floats2half2_rn(h0, h1);
            }
}

// ---------------------------------------------------------------------------
// GEMM3 (fp16): ys[slot] = fp16(score * (H[slot] @ Wd^T)). CTA: 128x128.
// 256 threads, 8 warps 2x4, warp 64x32. mbarrier pipeline. 2 CTAs/SM.
// ---------------------------------------------------------------------------
__global__ void __launch_bounds__(256, 2) g3_kernel() {
    extern __shared__ uint32_t sm[];
    __shared__ __align__(8) uint64_t mbs[2 * NSTG];
    __shared__ float sScr[128];
    const int tid = threadIdx.x, lane = tid & 31, w = tid >> 5;
    const int wm = w >> 2, wn = w & 3;                // 2x4 warp grid
    const int ql = lane >> 2, qc = lane & 3;
    const int e = blockIdx.z, bm = blockIdx.x, bn = blockIdx.y;
    const uint32_t sbase = smem_u32(sm);
    const uint32_t fullb = smem_u32(mbs), emptyb = fullb + NSTG * 8;

    if (tid == 0) {
        #pragma unroll
        for (int s = 0; s < NSTG; s++) {
            MB_INIT(fullb + 8 * s, 256);
            MB_INIT(emptyb + 8 * s, 256);
        }
    }
    if (tid < 128) sScr[tid] = g_scr[e * CAP + bm * 128 + tid];

    const int r4 = tid >> 2, ck = tid & 3;
    const __half* ap0 = g_Hh + ((size_t)e * CAP + (size_t)bm * 128 + r4) * H_FF + ck * 8;
    const __half* ap1 = ap0 + (size_t)64 * H_FF;
    const size_t bb = ((size_t)e * D_MODEL + (size_t)bn * 128 + r4) * H_FF + ck * 8;
    const __half* bp0 = g_Wdh + bb;
    const __half* bp1 = g_Wdh + bb + (size_t)64 * H_FF;
    const uint32_t ad0 = sbase + r4 * 80 + ck * 16, ad1 = ad0 + 64 * 80;
    const uint32_t bd0 = sbase + G3_B + r4 * 80 + ck * 16, bd1 = bd0 + 64 * 80;

    float acc[4][4][4];
    #pragma unroll
    for (int mi = 0; mi < 4; mi++)
        #pragma unroll
        for (int ni = 0; ni < 4; ni++)
            #pragma unroll
            for (int q = 0; q < 4; q++) acc[mi][ni][q] = 0.f;

    __syncthreads();   // mbarrier init + sScr visible

    #pragma unroll
    for (int s = 0; s < PFD; s++) {
        const uint32_t so = s * STG;
        const int ko = s * BK;
        cp16(ad0 + so, ap0 + ko); cp16(ad1 + so, ap1 + ko);
        cp16(bd0 + so, bp0 + ko); cp16(bd1 + so, bp1 + ko);
        CP_MB_ARRIVE(fullb + 8 * s);
    }

    for (int kt = 0; kt < NT3; kt++) {
        const int f = kt + PFD;
        if (f < NT3) {
            const int es = f % NSTG;
            if (f >= NSTG) mb_wait(emptyb + 8 * es, (f / NSTG - 1) & 1);
            const uint32_t so = es * STG;
            const int ko = f * BK;
            cp16(ad0 + so, ap0 + ko); cp16(ad1 + so, ap1 + ko);
            cp16(bd0 + so, bp0 + ko); cp16(bd1 + so, bp1 + ko);
            CP_MB_ARRIVE(fullb + 8 * es);
        }
        const int slot = kt % NSTG;
        mb_wait(fullb + 8 * slot, (kt / NSTG) & 1);

        const uint32_t* As = sm + slot * (STG / 4);
        const uint32_t* Bs = As + G3_B / 4;
        #pragma unroll
        for (int kk = 0; kk < 2; kk++) {
            const int kb = kk * 8 + qc;
            uint32_t af[4][4];
            #pragma unroll
            for (int mi = 0; mi < 4; mi++) {
                const int r = wm * 64 + mi * 16 + ql;
                af[mi][0] = As[r * 20 + kb];
                af[mi][1] = As[(r + 8) * 20 + kb];
                af[mi][2] = As[r * 20 + kb + 4];
                af[mi][3] = As[(r + 8) * 20 + kb + 4];
            }
            #pragma unroll
            for (int ni = 0; ni < 4; ni++) {
                const int nn = wn * 32 + ni * 8 + ql;
                uint32_t bw[2] = { Bs[nn * 20 + kb], Bs[nn * 20 + kb + 4] };
                #pragma unroll
                for (int mi = 0; mi < 4; mi++)
                    mma16(acc[mi][ni], af[mi], bw);
            }
        }
        MB_ARRIVE(emptyb + 8 * slot);
    }

    // epilogue: scale by score, fp16 coalesced stores to slot buffer
    const size_t rowBase = (size_t)e * CAP + (size_t)bm * 128;
    const int colBase = bn * 128 + wn * 32;
    #pragma unroll
    for (int mi = 0; mi < 4; mi++) {
        #pragma unroll
        for (int q2 = 0; q2 < 2; q2++) {
            const int r = wm * 64 + mi * 16 + ql + q2 * 8;
            const float sc = sScr[r];
            __half* yrow = g_ys + (rowBase + r) * D_MODEL + colBase;
            #pragma unroll
            for (int ni = 0; ni < 4; ni++) {
                const int n0 = ni * 8 + 2 * qc;
                *(__half2*)(yrow + n0) = __floats2half2_rn(
                    acc[mi][ni][q2 * 2] * sc, acc[mi][ni][q2 * 2 + 1] * sc);
            }
        }
    }
}

// ---------------------------------------------------------------------------
extern "C" void kernel_launch(void* const* d_in, const int* in_sizes, int n_in,
                              void* d_out, int out_size) {
    (void)in_sizes; (void)n_in; (void)out_size;
    const float* x   = (const float*)d_in[0];
    const int*   idx = (const int*)d_in[1];
    const float* scr = (const float*)d_in[2];
    const float* Wg  = (const float*)d_in[3];
    const float* Wu  = (const float*)d_in[4];
    const float* Wd  = (const float*)d_in[5];
    float* y = (float*)d_out;

    const int n4x = NTOK * D_MODEL / 4;
    prep_kernel<<<(n4x + 255) / 256, 256>>>((const float4*)x, n4x);
    route_kernel<<<SLOTS / 256, 256>>>(idx, scr);

    __half* gg; cudaGetSymbolAddress((void**)&gg, g_Wgh);
    __half* gu; cudaGetSymbolAddress((void**)&gu, g_Wuh);
    __half* gd; cudaGetSymbolAddress((void**)&gd, g_Wdh);
    dim3 tga(D_MODEL / 64, D_MODEL / 32, 3 * NE);   // (32, 64, 24) superset grid
    trcvt_all_kernel<<<tga, 256>>>(Wg, Wu, Wd, gg, gu, gd);

    cudaFuncSetAttribute(g1_kernel, cudaFuncAttributeMaxDynamicSharedMemorySize, SMEM_SZ);
    cudaFuncSetAttribute(g3_kernel, cudaFuncAttributeMaxDynamicSharedMemorySize, SMEM_SZ);

    dim3 grid1(CAP / 128, H_FF / 64, NE);     // (16, 22, 8)
    g1_kernel<<<grid1, 256, SMEM_SZ>>>();
    dim3 grid3(CAP / 128, D_MODEL / 128, NE); // (16, 16, 8)
    g3_kernel<<<grid3, 256, SMEM_SZ>>>();

    combine_kernel<<<NTOK * (D_MODEL / 4) / 256, 256>>>((float4*)y);
}

// round 17
// speedup vs baseline: 1.5046x; 1.0029x over previous
#include <cuda_runtime.h>
#include <cuda_fp16.h>
#include <stdint.h>

#define D_MODEL 2048
#define H_FF    1408
#define NE      8
#define NTOK    8192
#define SLOTS   16384
#define CAP     2048
#define BK      32                 // halfs per k-tile (64B rows)

#define NT1     (D_MODEL / BK)     // 64
#define NT3     (H_FF / BK)        // 44

#define NSTG    5                  // pipeline stages
#define PFD     1                  // prefetch distance; slip bound = NSTG-PFD = 4

// smem stage layout (bytes): rows padded to 80B (20 words; conflict-free)
#define G1_BG   10240
#define G1_BU   15360
#define G3_B    10240
#define STG     20480
#define SMEM_SZ (NSTG * STG)       // 102400

// ---------------- scratch ----------------
__device__ int    g_cnt[NE];
__device__ int    g_tok[SLOTS];
__device__ float  g_scr[SLOTS];
__device__ int    g_posA[NTOK];
__device__ int    g_posB[NTOK];
__device__ __half g_xh [(size_t)NTOK * D_MODEL];           // fp16 [tok][d]
__device__ __half g_Wgh[(size_t)NE * H_FF * D_MODEL];      // [e][h][d]
__device__ __half g_Wuh[(size_t)NE * H_FF * D_MODEL];      // [e][h][d]
__device__ __half g_Wdh[(size_t)NE * D_MODEL * H_FF];      // [e][d][h]
__device__ __half g_Hh [(size_t)SLOTS * H_FF];             // [slot][h]
__device__ __half g_ys [(size_t)SLOTS * D_MODEL];          // scored down partials (fp16)

// ---------------- helpers ----------------
__device__ __forceinline__ uint32_t smem_u32(const void* p) {
    uint32_t a;
    asm("{ .reg .u64 t; cvta.to.shared.u64 t, %1; cvt.u32.u64 %0, t; }" : "=r"(a) : "l"(p));
    return a;
}
__device__ __forceinline__ void cp16(uint32_t dst, const void* src) {
    asm volatile("cp.async.cg.shared.global [%0], [%1], 16;" :: "r"(dst), "l"(src));
}
#define MB_INIT(a, c) asm volatile("mbarrier.init.shared.b64 [%0], %1;" :: "r"(a), "r"(c) : "memory")
// plain arrive (implicit release) — r14 showed explicit .release.cta + elected
// arrives cost a per-ktile fence/divergence and regressed 45%; keep this form.
#define MB_ARRIVE(a)  asm volatile("mbarrier.arrive.shared.b64 _, [%0];" :: "r"(a) : "memory")
// .noinc is load-bearing (round-10 deadlock without it)
#define CP_MB_ARRIVE(a) asm volatile("cp.async.mbarrier.arrive.noinc.shared::cta.b64 [%0];" :: "r"(a) : "memory")

__device__ __forceinline__ void mb_wait(uint32_t mbar, uint32_t parity) {
    uint32_t done;
    asm volatile(
        "{ .reg .pred p; mbarrier.try_wait.parity.acquire.cta.shared::cta.b64 p, [%1], %2; selp.b32 %0, 1, 0, p; }"
        : "=r"(done) : "r"(mbar), "r"(parity) : "memory");
    if (!done) {
        asm volatile(
            "{ .reg .pred P1;\n"
            "WL_%=: mbarrier.try_wait.parity.acquire.cta.shared::cta.b64 P1, [%0], %1, 0x989680;\n"
            "@P1 bra.uni WD_%=;\n"
            "bra.uni WL_%=;\n"
            "WD_%=: }"
            :: "r"(mbar), "r"(parity) : "memory");
    }
}

__device__ __forceinline__ void mma16(float* d, const uint32_t* a, const uint32_t* b) {
    asm volatile(
        "mma.sync.aligned.m16n8k16.row.col.f32.f16.f16.f32 "
        "{%0,%1,%2,%3}, {%4,%5,%6,%7}, {%8,%9}, {%0,%1,%2,%3};\n"
        : "+f"(d[0]), "+f"(d[1]), "+f"(d[2]), "+f"(d[3])
        : "r"(a[0]), "r"(a[1]), "r"(a[2]), "r"(a[3]), "r"(b[0]), "r"(b[1]));
}
__device__ __forceinline__ uint32_t h2u(float a, float b) {
    __half2 h = __floats2half2_rn(a, b);
    return *(uint32_t*)&h;
}

// ---------------- pre-pass kernels ----------------
__global__ void prep_kernel(const float4* __restrict__ x, int n4) {
    int i = blockIdx.x * blockDim.x + threadIdx.x;
    if (i < n4) {
        float4 v = x[i];
        uint2 o;
        o.x = h2u(v.x, v.y);
        o.y = h2u(v.z, v.w);
        ((uint2*)g_xh)[i] = o;
    }
    if (blockIdx.x == 0 && threadIdx.x < NE) g_cnt[threadIdx.x] = 0;
}

__global__ void route_kernel(const int* __restrict__ idx, const float* __restrict__ scr) {
    int s = blockIdx.x * blockDim.x + threadIdx.x;
    if (s < SLOTS) {
        int e = idx[s];
        int p = atomicAdd(&g_cnt[e], 1);
        int dst = e * CAP + p;
        g_tok[dst] = s >> 1;             // TOP_K = 2
        g_scr[dst] = scr[s];
        if (s & 1) g_posB[s >> 1] = dst; else g_posA[s >> 1] = dst;
    }
}

// transpose+convert body: src [K][N] fp32 -> dst [N][K] fp16, tile 64k x 32n
__device__ __forceinline__ void trcvt_body(const float* S, __half* D, int K, int N,
                                           int k0, int n0, int tid) {
    __shared__ float t[64][33];
    #pragma unroll
    for (int it = 0; it < 2; it++) {
        int idx = tid + it * 256;
        int kr = idx >> 3, c4 = (idx & 7) * 4;
        float4 v = *(const float4*)(S + (size_t)(k0 + kr) * N + n0 + c4);
        t[kr][c4] = v.x; t[kr][c4 + 1] = v.y; t[kr][c4 + 2] = v.z; t[kr][c4 + 3] = v.w;
    }
    __syncthreads();
    #pragma unroll
    for (int it = 0; it < 4; it++) {
        int idx = tid + it * 256;
        int n = idx >> 5, k2 = idx & 31;
        __half2 h = __floats2half2_rn(t[2 * k2][n], t[2 * k2 + 1][n]);
        ((__half2*)(D + (size_t)(n0 + n) * K + k0))[k2] = h;
    }
}

// all three weight transposes in ONE launch (z<8 Wg, z<16 Wu, else Wd)
__global__ void trcvt_all_kernel(const float* __restrict__ Wg, const float* __restrict__ Wu,
                                 const float* __restrict__ Wd,
                                 __half* __restrict__ dg, __half* __restrict__ du,
                                 __half* __restrict__ dd) {
    const int z = blockIdx.z;
    const float* S;
    __half* D;
    int K, N;
    if (z < 16) {
        const int e = z & 7;
        S = ((z < 8) ? Wg : Wu) + (size_t)e * D_MODEL * H_FF;
        D = ((z < 8) ? dg : du) + (size_t)e * H_FF * D_MODEL;
        K = D_MODEL; N = H_FF;
    } else {
        const int e = z - 16;
        S = Wd + (size_t)e * H_FF * D_MODEL;
        D = dd + (size_t)e * D_MODEL * H_FF;
        K = H_FF; N = D_MODEL;
    }
    const int k0 = blockIdx.x * 64, n0 = blockIdx.y * 32;
    if (k0 >= K || n0 >= N) return;
    trcvt_body(S, D, K, N, k0, n0, threadIdx.x);
}

// combine: y[t] = ys[posA[t]] + ys[posB[t]]   (ys fp16, y fp32)
__global__ void combine_kernel(float4* __restrict__ y) {
    int i = blockIdx.x * blockDim.x + threadIdx.x;   // over NTOK * 512
    int t = i >> 9, c = i & 511;
    const __half2* a = (const __half2*)(g_ys + (size_t)g_posA[t] * D_MODEL) + c * 2;
    const __half2* b = (const __half2*)(g_ys + (size_t)g_posB[t] * D_MODEL) + c * 2;
    __half2 a0 = a[0], a1 = a[1], b0 = b[0], b1 = b[1];
    float2 fa0 = __half22float2(a0), fa1 = __half22float2(a1);
    float2 fb0 = __half22float2(b0), fb1 = __half22float2(b1);
    float4 r;
    r.x = fa0.x + fb0.x; r.y = fa0.y + fb0.y;
    r.z = fa1.x + fb1.x; r.w = fa1.y + fb1.y;
    y[i] = r;
}

// ---------------------------------------------------------------------------
// GEMM1+2 fused (fp16). CTA: 128 slots x 64 h, gate+up. 256 threads, 8 warps
// 4x2, warp 32x32 per matrix. 5-stage mbarrier pipeline, free-running warps
// (slip bound NSTG-PFD = 4), 2 CTAs/SM.
// ---------------------------------------------------------------------------
__global__ void __launch_bounds__(256, 2) g1_kernel() {
    extern __shared__ uint32_t sm[];
    __shared__ __align__(8) uint64_t mbs[2 * NSTG];
    const int tid = threadIdx.x, lane = tid & 31, w = tid >> 5;
    const int wm = w >> 1, wn = w & 1;                // 4x2 warp grid
    const int ql = lane >> 2, qc = lane & 3;
    const int e = blockIdx.z, bm = blockIdx.x, bn = blockIdx.y;
    const uint32_t sbase = smem_u32(sm);
    const uint32_t fullb = smem_u32(mbs), emptyb = fullb + NSTG * 8;

    if (tid == 0) {
        #pragma unroll
        for (int s = 0; s < NSTG; s++) {
            MB_INIT(fullb + 8 * s, 256);
            MB_INIT(emptyb + 8 * s, 256);
        }
    }

    // loaders: A rows r4 and r4+64 (chunk ck); Bg/Bu row r4 (64 rows)
    const int r4 = tid >> 2, ck = tid & 3;
    const __half* ap0 = g_xh + (size_t)g_tok[e * CAP + bm * 128 + r4] * D_MODEL + ck * 8;
    const __half* ap1 = g_xh + (size_t)g_tok[e * CAP + bm * 128 + r4 + 64] * D_MODEL + ck * 8;
    const size_t bb = ((size_t)e * H_FF + (size_t)bn * 64 + r4) * D_MODEL + ck * 8;
    const __half* gp = g_Wgh + bb;
    const __half* up = g_Wuh + bb;
    const uint32_t ad0 = sbase + r4 * 80 + ck * 16, ad1 = ad0 + 64 * 80;
    const uint32_t gd = sbase + G1_BG + r4 * 80 + ck * 16;
    const uint32_t ud = sbase + G1_BU + r4 * 80 + ck * 16;

    float accg[2][4][4], accu[2][4][4];
    #pragma unroll
    for (int mi = 0; mi < 2; mi++)
        #pragma unroll
        for (int ni = 0; ni < 4; ni++)
            #pragma unroll
            for (int q = 0; q < 4; q++) { accg[mi][ni][q] = 0.f; accu[mi][ni][q] = 0.f; }

    __syncthreads();   // mbarrier init visible

    #pragma unroll
    for (int s = 0; s < PFD; s++) {
        const uint32_t so = s * STG;
        const int ko = s * BK;
        cp16(ad0 + so, ap0 + ko); cp16(ad1 + so, ap1 + ko);
        cp16(gd + so, gp + ko);   cp16(ud + so, up + ko);
        CP_MB_ARRIVE(fullb + 8 * s);
    }

    for (int kt = 0; kt < NT1; kt++) {
        const int f = kt + PFD;
        if (f < NT1) {
            const int es = f % NSTG;
            if (f >= NSTG) mb_wait(emptyb + 8 * es, (f / NSTG - 1) & 1);
            const uint32_t so = es * STG;
            const int ko = f * BK;
            cp16(ad0 + so, ap0 + ko); cp16(ad1 + so, ap1 + ko);
            cp16(gd + so, gp + ko);   cp16(ud + so, up + ko);
            CP_MB_ARRIVE(fullb + 8 * es);
        }
        const int slot = kt % NSTG;
        mb_wait(fullb + 8 * slot, (kt / NSTG) & 1);

        const uint32_t* As = sm + slot * (STG / 4);
        const uint32_t* Bg = As + G1_BG / 4;
        const uint32_t* Bu = As + G1_BU / 4;
        #pragma unroll
        for (int kk = 0; kk < 2; kk++) {
            const int kb = kk * 8 + qc;
            uint32_t af[2][4];
            #pragma unroll
            for (int mi = 0; mi < 2; mi++) {
                const int r = wm * 32 + mi * 16 + ql;
                af[mi][0] = As[r * 20 + kb];
                af[mi][1] = As[(r + 8) * 20 + kb];
                af[mi][2] = As[r * 20 + kb + 4];
                af[mi][3] = As[(r + 8) * 20 + kb + 4];
            }
            #pragma unroll
            for (int ni = 0; ni < 4; ni++) {
                const int nn = wn * 32 + ni * 8 + ql;
                uint32_t bg[2] = { Bg[nn * 20 + kb], Bg[nn * 20 + kb + 4] };
                uint32_t bu[2] = { Bu[nn * 20 + kb], Bu[nn * 20 + kb + 4] };
                #pragma unroll
                for (int mi = 0; mi < 2; mi++) {
                    mma16(accg[mi][ni], af[mi], bg);
                    mma16(accu[mi][ni], af[mi], bu);
                }
            }
        }
        MB_ARRIVE(emptyb + 8 * slot);
    }

    // epilogue: h = silu(g)*u -> fp16 H
    const size_t rowBase = (size_t)e * CAP + (size_t)bm * 128;
    const int colBase = bn * 64 + wn * 32;
    #pragma unroll
    for (int mi = 0; mi < 2; mi++)
        #pragma unroll
        for (int ni = 0; ni < 4; ni++)
            #pragma unroll
            for (int q2 = 0; q2 < 2; q2++) {
                const int r = wm * 32 + mi * 16 + ql + q2 * 8;
                float g0 = accg[mi][ni][q2 * 2],     u0 = accu[mi][ni][q2 * 2];
                float g1 = accg[mi][ni][q2 * 2 + 1], u1 = accu[mi][ni][q2 * 2 + 1];
                float h0 = (g0 / (1.f + __expf(-g0))) * u0;
                float h1 = (g1 / (1.f + __expf(-g1))) * u1;
                *(__half2*)(g_Hh + (rowBase + r) * H_FF + colBase + ni * 8 + 2 * qc) =
                    __floats2half2_rn(h0, h1);
            }
}

// ---------------------------------------------------------------------------
// GEMM3 (fp16): ys[slot] = fp16(score * (H[slot] @ Wd^T)). CTA: 128x128.
// 256 threads, 8 warps 2x4, warp 64x32. mbarrier pipeline. 2 CTAs/SM.
// ---------------------------------------------------------------------------
__global__ void __launch_bounds__(256, 2) g3_kernel() {
    extern __shared__ uint32_t sm[];
    __shared__ __align__(8) uint64_t mbs[2 * NSTG];
    __shared__ float sScr[128];
    const int tid = threadIdx.x, lane = tid & 31, w = tid >> 5;
    const int wm = w >> 2, wn = w & 3;                // 2x4 warp grid
    const int ql = lane >> 2, qc = lane & 3;
    const int e = blockIdx.z, bm = blockIdx.x, bn = blockIdx.y;
    const uint32_t sbase = smem_u32(sm);
    const uint32_t fullb = smem_u32(mbs), emptyb = fullb + NSTG * 8;

    if (tid == 0) {
        #pragma unroll
        for (int s = 0; s < NSTG; s++) {
            MB_INIT(fullb + 8 * s, 256);
            MB_INIT(emptyb + 8 * s, 256);
        }
    }
    if (tid < 128) sScr[tid] = g_scr[e * CAP + bm * 128 + tid];

    const int r4 = tid >> 2, ck = tid & 3;
    const __half* ap0 = g_Hh + ((size_t)e * CAP + (size_t)bm * 128 + r4) * H_FF + ck * 8;
    const __half* ap1 = ap0 + (size_t)64 * H_FF;
    const size_t bb = ((size_t)e * D_MODEL + (size_t)bn * 128 + r4) * H_FF + ck * 8;
    const __half* bp0 = g_Wdh + bb;
    const __half* bp1 = g_Wdh + bb + (size_t)64 * H_FF;
    const uint32_t ad0 = sbase + r4 * 80 + ck * 16, ad1 = ad0 + 64 * 80;
    const uint32_t bd0 = sbase + G3_B + r4 * 80 + ck * 16, bd1 = bd0 + 64 * 80;

    float acc[4][4][4];
    #pragma unroll
    for (int mi = 0; mi < 4; mi++)
        #pragma unroll
        for (int ni = 0; ni < 4; ni++)
            #pragma unroll
            for (int q = 0; q < 4; q++) acc[mi][ni][q] = 0.f;

    __syncthreads();   // mbarrier init + sScr visible

    #pragma unroll
    for (int s = 0; s < PFD; s++) {
        const uint32_t so = s * STG;
        const int ko = s * BK;
        cp16(ad0 + so, ap0 + ko); cp16(ad1 + so, ap1 + ko);
        cp16(bd0 + so, bp0 + ko); cp16(bd1 + so, bp1 + ko);
        CP_MB_ARRIVE(fullb + 8 * s);
    }

    for (int kt = 0; kt < NT3; kt++) {
        const int f = kt + PFD;
        if (f < NT3) {
            const int es = f % NSTG;
            if (f >= NSTG) mb_wait(emptyb + 8 * es, (f / NSTG - 1) & 1);
            const uint32_t so = es * STG;
            const int ko = f * BK;
            cp16(ad0 + so, ap0 + ko); cp16(ad1 + so, ap1 + ko);
            cp16(bd0 + so, bp0 + ko); cp16(bd1 + so, bp1 + ko);
            CP_MB_ARRIVE(fullb + 8 * es);
        }
        const int slot = kt % NSTG;
        mb_wait(fullb + 8 * slot, (kt / NSTG) & 1);

        const uint32_t* As = sm + slot * (STG / 4);
        const uint32_t* Bs = As + G3_B / 4;
        #pragma unroll
        for (int kk = 0; kk < 2; kk++) {
            const int kb = kk * 8 + qc;
            uint32_t af[4][4];
            #pragma unroll
            for (int mi = 0; mi < 4; mi++) {
                const int r = wm * 64 + mi * 16 + ql;
                af[mi][0] = As[r * 20 + kb];
                af[mi][1] = As[(r + 8) * 20 + kb];
                af[mi][2] = As[r * 20 + kb + 4];
                af[mi][3] = As[(r + 8) * 20 + kb + 4];
            }
            #pragma unroll
            for (int ni = 0; ni < 4; ni++) {
                const int nn = wn * 32 + ni * 8 + ql;
                uint32_t bw[2] = { Bs[nn * 20 + kb], Bs[nn * 20 + kb + 4] };
                #pragma unroll
                for (int mi = 0; mi < 4; mi++)
                    mma16(acc[mi][ni], af[mi], bw);
            }
        }
        MB_ARRIVE(emptyb + 8 * slot);
    }

    // epilogue: scale by score, fp16 coalesced stores to slot buffer
    const size_t rowBase = (size_t)e * CAP + (size_t)bm * 128;
    const int colBase = bn * 128 + wn * 32;
    #pragma unroll
    for (int mi = 0; mi < 4; mi++) {
        #pragma unroll
        for (int q2 = 0; q2 < 2; q2++) {
            const int r = wm * 64 + mi * 16 + ql + q2 * 8;
            const float sc = sScr[r];
            __half* yrow = g_ys + (rowBase + r) * D_MODEL + colBase;
            #pragma unroll
            for (int ni = 0; ni < 4; ni++) {
                const int n0 = ni * 8 + 2 * qc;
                *(__half2*)(yrow + n0) = __floats2half2_rn(
                    acc[mi][ni][q2 * 2] * sc, acc[mi][ni][q2 * 2 + 1] * sc);
            }
        }
    }
}

// ---------------------------------------------------------------------------
extern "C" void kernel_launch(void* const* d_in, const int* in_sizes, int n_in,
                              void* d_out, int out_size) {
    (void)in_sizes; (void)n_in; (void)out_size;
    const float* x   = (const float*)d_in[0];
    const int*   idx = (const int*)d_in[1];
    const float* scr = (const float*)d_in[2];
    const float* Wg  = (const float*)d_in[3];
    const float* Wu  = (const float*)d_in[4];
    const float* Wd  = (const float*)d_in[5];
    float* y = (float*)d_out;

    const int n4x = NTOK * D_MODEL / 4;
    prep_kernel<<<(n4x + 255) / 256, 256>>>((const float4*)x, n4x);
    route_kernel<<<SLOTS / 256, 256>>>(idx, scr);

    __half* gg; cudaGetSymbolAddress((void**)&gg, g_Wgh);
    __half* gu; cudaGetSymbolAddress((void**)&gu, g_Wuh);
    __half* gd; cudaGetSymbolAddress((void**)&gd, g_Wdh);
    dim3 tga(D_MODEL / 64, D_MODEL / 32, 3 * NE);   // (32, 64, 24) superset grid
    trcvt_all_kernel<<<tga, 256>>>(Wg, Wu, Wd, gg, gu, gd);

    cudaFuncSetAttribute(g1_kernel, cudaFuncAttributeMaxDynamicSharedMemorySize, SMEM_SZ);
    cudaFuncSetAttribute(g3_kernel, cudaFuncAttributeMaxDynamicSharedMemorySize, SMEM_SZ);

    dim3 grid1(CAP / 128, H_FF / 64, NE);     // (16, 22, 8)
    g1_kernel<<<grid1, 256, SMEM_SZ>>>();
    dim3 grid3(CAP / 128, D_MODEL / 128, NE); // (16, 16, 8)
    g3_kernel<<<grid3, 256, SMEM_SZ>>>();

    combine_kernel<<<NTOK * (D_MODEL / 4) / 256, 256>>>((float4*)y);
}